// round 3
// baseline (speedup 1.0000x reference)
#include <cuda_runtime.h>

// Problem shape: x is (32, 1, 1024, 1024) fp32.
#define IMG_N 32
#define HDIM  1024
#define WDIM  1024

__device__ double g_acc[2 * IMG_N];  // [0..31] = sum(z), [32..63] = sum(z^2)

__global__ void zero_acc_kernel() {
    if (threadIdx.x < 2 * IMG_N) g_acc[threadIdx.x] = 0.0;
}

// Compute 4 consecutive z values for (row, col..col+3) of one image.
// z = center - (L + 2*DL + 4*D + 8*DR + 16*R + 32*UR + 64*U + 128*UL) / 255
// with zero padding outside the image.
__device__ __forceinline__ void compute_z4(const float* __restrict__ base,
                                           int row, int col, float z[4]) {
    const float INV255 = 1.0f / 255.0f;
    const float* rc = base + (size_t)row * WDIM;

    float4 c  = *(const float4*)(rc + col);
    float  cl = (col > 0)        ? __ldg(rc + col - 1) : 0.0f;
    float  cr = (col + 4 < WDIM) ? __ldg(rc + col + 4) : 0.0f;

    float4 u = make_float4(0.f, 0.f, 0.f, 0.f);
    float  ul = 0.f, ur = 0.f;
    if (row > 0) {
        const float* ru = rc - WDIM;
        u = *(const float4*)(ru + col);
        if (col > 0)        ul = __ldg(ru + col - 1);
        if (col + 4 < WDIM) ur = __ldg(ru + col + 4);
    }

    float4 d = make_float4(0.f, 0.f, 0.f, 0.f);
    float  dl = 0.f, dr = 0.f;
    if (row < HDIM - 1) {
        const float* rd = rc + WDIM;
        d = *(const float4*)(rd + col);
        if (col > 0)        dl = __ldg(rd + col - 1);
        if (col + 4 < WDIM) dr = __ldg(rd + col + 4);
    }

    z[0] = c.x - (cl  + 2.f*dl  + 4.f*d.x + 8.f*d.y + 16.f*c.y + 32.f*u.y + 64.f*u.x + 128.f*ul ) * INV255;
    z[1] = c.y - (c.x + 2.f*d.x + 4.f*d.y + 8.f*d.z + 16.f*c.z + 32.f*u.z + 64.f*u.y + 128.f*u.x) * INV255;
    z[2] = c.z - (c.y + 2.f*d.y + 4.f*d.z + 8.f*d.w + 16.f*c.w + 32.f*u.w + 64.f*u.z + 128.f*u.y) * INV255;
    z[3] = c.w - (c.z + 2.f*d.z + 4.f*d.w + 8.f*dr  + 16.f*cr  + 32.f*ur  + 64.f*u.w + 128.f*u.z) * INV255;
}

// Pass 1: one block per image row. Compute z, reduce sum and sum-of-squares,
// accumulate into per-image double accumulators.
__global__ void __launch_bounds__(256) ltpe_pass1(const float* __restrict__ x) {
    int row = blockIdx.x & (HDIM - 1);
    int img = blockIdx.x >> 10;
    const float* base = x + (size_t)img * HDIM * WDIM;
    int col = threadIdx.x * 4;

    float z[4];
    compute_z4(base, row, col, z);

    float s  = z[0] + z[1] + z[2] + z[3];
    float ss = z[0]*z[0] + z[1]*z[1] + z[2]*z[2] + z[3]*z[3];

    #pragma unroll
    for (int o = 16; o > 0; o >>= 1) {
        s  += __shfl_xor_sync(0xffffffffu, s,  o);
        ss += __shfl_xor_sync(0xffffffffu, ss, o);
    }

    __shared__ float ws[8], wss[8];
    int lane = threadIdx.x & 31;
    int wid  = threadIdx.x >> 5;
    if (lane == 0) { ws[wid] = s; wss[wid] = ss; }
    __syncthreads();

    if (threadIdx.x == 0) {
        float S = 0.f, SS = 0.f;
        #pragma unroll
        for (int i = 0; i < 8; i++) { S += ws[i]; SS += wss[i]; }
        atomicAdd(&g_acc[img],         (double)S);
        atomicAdd(&g_acc[IMG_N + img], (double)SS);
    }
}

// Pass 2: recompute z (cheaper than storing/re-reading it), normalize, write.
__global__ void __launch_bounds__(256) ltpe_pass2(const float* __restrict__ x,
                                                  float* __restrict__ out) {
    int row = blockIdx.x & (HDIM - 1);
    int img = blockIdx.x >> 10;

    __shared__ float s_mean, s_inv;
    if (threadIdx.x == 0) {
        const double N = (double)(HDIM * WDIM);
        double m   = g_acc[img] / N;
        double var = g_acc[IMG_N + img] / N - m * m;
        s_mean = (float)m;
        // eps rescale: o = 0.5 z + 0.5 => (o-mu_o)/sqrt(var_o+1e-5)
        //            = (z-mu_z)/sqrt(var_z + 4e-5)
        s_inv  = (float)rsqrt(var + 4e-5);
    }

    const float* base = x + (size_t)img * HDIM * WDIM;
    int col = threadIdx.x * 4;

    float z[4];
    compute_z4(base, row, col, z);

    __syncthreads();
    float m = s_mean, inv = s_inv;

    float4 o;
    o.x = (z[0] - m) * inv;
    o.y = (z[1] - m) * inv;
    o.z = (z[2] - m) * inv;
    o.w = (z[3] - m) * inv;

    *(float4*)(out + (size_t)img * HDIM * WDIM + (size_t)row * WDIM + col) = o;
}

extern "C" void kernel_launch(void* const* d_in, const int* in_sizes, int n_in,
                              void* d_out, int out_size) {
    const float* x   = (const float*)d_in[0];
    float*       out = (float*)d_out;

    dim3 grid(IMG_N * HDIM);   // one block per image row
    dim3 block(256);           // 256 threads x float4 = 1024 columns

    zero_acc_kernel<<<1, 64>>>();
    ltpe_pass1<<<grid, block>>>(x);
    ltpe_pass2<<<grid, block>>>(x, out);
}

// round 4
// speedup vs baseline: 1.4874x; 1.4874x over previous
#include <cuda_runtime.h>

// x: (32, 1, 1024, 1024) fp32. out same shape.
#define IMG_N 32
#define HDIM  1024
#define WDIM  1024
#define RSTRIP 16                      // rows per block strip
#define STRIPS (HDIM / RSTRIP)         // 64 strips per image
#define NBLOCKS (IMG_N * STRIPS)       // 2048 blocks per pass

// Per-block partial sums (written unconditionally by pass1 -> no zeroing needed).
__device__ double g_psum[NBLOCKS];
__device__ double g_pss[NBLOCKS];

// Load one image row's 4-wide chunk + left/right halo scalars (zero outside image).
__device__ __forceinline__ void load_row(const float* __restrict__ base, int row,
                                         int col, float4& v, float& l, float& r) {
    if (row < 0 || row >= HDIM) {
        v = make_float4(0.f, 0.f, 0.f, 0.f); l = 0.f; r = 0.f; return;
    }
    const float* p = base + (size_t)row * WDIM;
    v = *(const float4*)(p + col);
    l = (col > 0)        ? __ldg(p + col - 1) : 0.f;  // L1 hit: neighbor thread's line
    r = (col + 4 < WDIM) ? __ldg(p + col + 4) : 0.f;
}

// z = center - (L + 2*DL + 4*D + 8*DR + 16*R + 32*UR + 64*U + 128*UL)/255
// u = row-1 ("up"), d = row+1 ("down"), matching the reference offsets.
__device__ __forceinline__ void stencil4(const float4& u, float ul, float ur,
                                         const float4& c, float cl, float cr,
                                         const float4& d, float dl, float dr,
                                         float z[4]) {
    const float INV255 = 1.0f / 255.0f;
    z[0] = c.x - (cl  + 2.f*dl  + 4.f*d.x + 8.f*d.y + 16.f*c.y + 32.f*u.y + 64.f*u.x + 128.f*ul ) * INV255;
    z[1] = c.y - (c.x + 2.f*d.x + 4.f*d.y + 8.f*d.z + 16.f*c.z + 32.f*u.z + 64.f*u.y + 128.f*u.x) * INV255;
    z[2] = c.z - (c.y + 2.f*d.y + 4.f*d.z + 8.f*d.w + 16.f*c.w + 32.f*u.w + 64.f*u.z + 128.f*u.y) * INV255;
    z[3] = c.w - (c.z + 2.f*d.z + 4.f*d.w + 8.f*dr  + 16.f*cr  + 32.f*ur  + 64.f*u.w + 128.f*u.z) * INV255;
}

// Pass 1: one block per 16-row strip. Rolling registers: each row loaded once.
__global__ void __launch_bounds__(256) ltpe_pass1(const float* __restrict__ x) {
    int strip = blockIdx.x % STRIPS;
    int img   = blockIdx.x / STRIPS;
    int r0    = strip * RSTRIP;
    const float* base = x + (size_t)img * HDIM * WDIM;
    int col = threadIdx.x * 4;

    float4 pv, cv, nv;
    float pl, pr, cl, cr, nl, nr;
    load_row(base, r0 - 1, col, pv, pl, pr);
    load_row(base, r0,     col, cv, cl, cr);

    float s = 0.f, ss = 0.f;
    #pragma unroll
    for (int i = 0; i < RSTRIP; i++) {
        load_row(base, r0 + i + 1, col, nv, nl, nr);
        float z[4];
        stencil4(pv, pl, pr, cv, cl, cr, nv, nl, nr, z);
        s  += (z[0] + z[1]) + (z[2] + z[3]);
        ss += (z[0]*z[0] + z[1]*z[1]) + (z[2]*z[2] + z[3]*z[3]);
        pv = cv; pl = cl; pr = cr;
        cv = nv; cl = nl; cr = nr;
    }

    #pragma unroll
    for (int o = 16; o > 0; o >>= 1) {
        s  += __shfl_xor_sync(0xffffffffu, s,  o);
        ss += __shfl_xor_sync(0xffffffffu, ss, o);
    }
    __shared__ float ws[8], wss[8];
    int lane = threadIdx.x & 31, wid = threadIdx.x >> 5;
    if (lane == 0) { ws[wid] = s; wss[wid] = ss; }
    __syncthreads();
    if (threadIdx.x == 0) {
        float S = 0.f, SS = 0.f;
        #pragma unroll
        for (int i = 0; i < 8; i++) { S += ws[i]; SS += wss[i]; }
        g_psum[blockIdx.x] = (double)S;
        g_pss[blockIdx.x]  = (double)SS;
    }
}

// Pass 2: same strip structure; reduce this image's 64 partials (fixed-order
// smem tree -> deterministic), recompute stencil, normalize, write.
__global__ void __launch_bounds__(256) ltpe_pass2(const float* __restrict__ x,
                                                  float* __restrict__ out) {
    int strip = blockIdx.x % STRIPS;
    int img   = blockIdx.x / STRIPS;
    int r0    = strip * RSTRIP;

    __shared__ double rs[STRIPS], rss[STRIPS];
    __shared__ float s_mean, s_inv;
    if (threadIdx.x < STRIPS) {
        rs[threadIdx.x]  = g_psum[img * STRIPS + threadIdx.x];
        rss[threadIdx.x] = g_pss[img * STRIPS + threadIdx.x];
    }
    __syncthreads();
    #pragma unroll
    for (int o = STRIPS / 2; o > 0; o >>= 1) {
        if (threadIdx.x < o) {
            rs[threadIdx.x]  += rs[threadIdx.x + o];
            rss[threadIdx.x] += rss[threadIdx.x + o];
        }
        __syncthreads();
    }
    if (threadIdx.x == 0) {
        const double N = (double)HDIM * WDIM;
        double m   = rs[0] / N;
        double var = rss[0] / N - m * m;
        s_mean = (float)m;
        // o = 0.5*z + 0.5 and IN eps=1e-5  =>  normalize z with eps' = 4e-5
        s_inv = (float)rsqrt(var + 4e-5);
    }

    const float* base = x + (size_t)img * HDIM * WDIM;
    float* obase = out + (size_t)img * HDIM * WDIM;
    int col = threadIdx.x * 4;

    float4 pv, cv, nv;
    float pl, pr, cl, cr, nl, nr;
    load_row(base, r0 - 1, col, pv, pl, pr);
    load_row(base, r0,     col, cv, cl, cr);

    __syncthreads();
    float m = s_mean, inv = s_inv;

    #pragma unroll
    for (int i = 0; i < RSTRIP; i++) {
        load_row(base, r0 + i + 1, col, nv, nl, nr);
        float z[4];
        stencil4(pv, pl, pr, cv, cl, cr, nv, nl, nr, z);
        float4 o;
        o.x = (z[0] - m) * inv;
        o.y = (z[1] - m) * inv;
        o.z = (z[2] - m) * inv;
        o.w = (z[3] - m) * inv;
        *(float4*)(obase + (size_t)(r0 + i) * WDIM + col) = o;
        pv = cv; pl = cl; pr = cr;
        cv = nv; cl = nl; cr = nr;
    }
}

extern "C" void kernel_launch(void* const* d_in, const int* in_sizes, int n_in,
                              void* d_out, int out_size) {
    const float* x   = (const float*)d_in[0];
    float*       out = (float*)d_out;

    ltpe_pass1<<<NBLOCKS, 256>>>(x);
    ltpe_pass2<<<NBLOCKS, 256>>>(x, out);
}

// round 5
// speedup vs baseline: 1.6049x; 1.0789x over previous
#include <cuda_runtime.h>

// x: (32, 1, 1024, 1024) fp32. out same shape.
#define IMG_N 32
#define HDIM  1024
#define WDIM  1024
#define RSTRIP 16                      // rows per block strip
#define STRIPS (HDIM / RSTRIP)         // 64 strips per image
#define NBLOCKS (IMG_N * STRIPS)       // 2048 blocks per pass

// Per-block partial sums (written unconditionally by pass1 -> no zeroing needed).
__device__ double g_psum[NBLOCKS];
__device__ double g_pss[NBLOCKS];

// Load one row's 4-wide chunk + left/right halo scalars.
// INTERIOR: row guaranteed in [0, HDIM) -> no bounds check, clean batched loads.
template<bool INTERIOR>
__device__ __forceinline__ void load_row_t(const float* __restrict__ base, int row,
                                           int col, float4& v, float& l, float& r) {
    if (!INTERIOR) {
        if (row < 0 || row >= HDIM) {
            v = make_float4(0.f, 0.f, 0.f, 0.f); l = 0.f; r = 0.f; return;
        }
    }
    const float* p = base + (size_t)row * WDIM;
    v = *(const float4*)(p + col);
    l = (col > 0)        ? __ldg(p + col - 1) : 0.f;   // L1 hit (neighbor's line)
    r = (col + 4 < WDIM) ? __ldg(p + col + 4) : 0.f;
}

// z = center - (L + 2*DL + 4*D + 8*DR + 16*R + 32*UR + 64*U + 128*UL)/255
// u = row-1, d = row+1 (matches reference offsets; zero padding outside).
__device__ __forceinline__ void stencil4(const float4& u, float ul, float ur,
                                         const float4& c, float cl, float cr,
                                         const float4& d, float dl, float dr,
                                         float z[4]) {
    const float INV255 = 1.0f / 255.0f;
    z[0] = c.x - (cl  + 2.f*dl  + 4.f*d.x + 8.f*d.y + 16.f*c.y + 32.f*u.y + 64.f*u.x + 128.f*ul ) * INV255;
    z[1] = c.y - (c.x + 2.f*d.x + 4.f*d.y + 8.f*d.z + 16.f*c.z + 32.f*u.z + 64.f*u.y + 128.f*u.x) * INV255;
    z[2] = c.z - (c.y + 2.f*d.y + 4.f*d.z + 8.f*d.w + 16.f*c.w + 32.f*u.w + 64.f*u.z + 128.f*u.y) * INV255;
    z[3] = c.w - (c.z + 2.f*d.z + 4.f*d.w + 8.f*dr  + 16.f*cr  + 32.f*ur  + 64.f*u.w + 128.f*u.z) * INV255;
}

// ============ Pass 1: stats (sum z, sum z^2) over each 16-row strip ==========
// Ring of 5 rows, software-pipelined: at iter i, issue load of row r0+i+3,
// compute stencil for row r0+i from rows (i-1, i, i+1). ~3 vec loads in flight.
template<bool INTERIOR>
__device__ __forceinline__ void pass1_strip(const float* __restrict__ base,
                                            int r0, int col, float& s, float& ss) {
    float4 v[5]; float l[5], r[5];
    // Preload relative rows 0..3  (absolute rows r0-1 .. r0+2)
    #pragma unroll
    for (int k = 0; k < 4; k++)
        load_row_t<INTERIOR>(base, r0 - 1 + k, col, v[k], l[k], r[k]);

    s = 0.f; ss = 0.f;
    #pragma unroll
    for (int i = 0; i < RSTRIP; i++) {
        if (i < RSTRIP - 2) {                    // load rel row i+4 (abs r0+i+3)
            const int rel = (i + 4) % 5;
            load_row_t<INTERIOR>(base, r0 + i + 3, col, v[rel], l[rel], r[rel]);
        }
        const int a = i % 5, b = (i + 1) % 5, c = (i + 2) % 5;
        float z[4];
        stencil4(v[a], l[a], r[a], v[b], l[b], r[b], v[c], l[c], r[c], z);
        s  += (z[0] + z[1]) + (z[2] + z[3]);
        ss += (z[0]*z[0] + z[1]*z[1]) + (z[2]*z[2] + z[3]*z[3]);
    }
}

__global__ void __launch_bounds__(256) ltpe_pass1(const float* __restrict__ x) {
    int strip = blockIdx.x % STRIPS;
    int img   = blockIdx.x / STRIPS;
    int r0    = strip * RSTRIP;
    const float* base = x + (size_t)img * HDIM * WDIM;
    int col = threadIdx.x * 4;

    float s, ss;
    if (strip != 0 && strip != STRIPS - 1) pass1_strip<true >(base, r0, col, s, ss);
    else                                   pass1_strip<false>(base, r0, col, s, ss);

    #pragma unroll
    for (int o = 16; o > 0; o >>= 1) {
        s  += __shfl_xor_sync(0xffffffffu, s,  o);
        ss += __shfl_xor_sync(0xffffffffu, ss, o);
    }
    __shared__ float ws[8], wss[8];
    int lane = threadIdx.x & 31, wid = threadIdx.x >> 5;
    if (lane == 0) { ws[wid] = s; wss[wid] = ss; }
    __syncthreads();
    if (threadIdx.x == 0) {
        float S = 0.f, SS = 0.f;
        #pragma unroll
        for (int i = 0; i < 8; i++) { S += ws[i]; SS += wss[i]; }
        g_psum[blockIdx.x] = (double)S;
        g_pss[blockIdx.x]  = (double)SS;
    }
}

// ============ Pass 2: recompute stencil, normalize, stream out ===============
template<bool INTERIOR>
__device__ __forceinline__ void pass2_strip(const float* __restrict__ base,
                                            float* __restrict__ obase,
                                            int r0, int col, int img) {
    float4 v[5]; float l[5], r[5];
    // Issue pixel preloads FIRST so the DRAM round-trip overlaps the stats reduce.
    #pragma unroll
    for (int k = 0; k < 4; k++)
        load_row_t<INTERIOR>(base, r0 - 1 + k, col, v[k], l[k], r[k]);

    // Fixed-order stats reduction (deterministic).
    __shared__ double rs[STRIPS], rss[STRIPS];
    __shared__ float s_mean, s_inv;
    if (threadIdx.x < STRIPS) {
        rs[threadIdx.x]  = g_psum[img * STRIPS + threadIdx.x];
        rss[threadIdx.x] = g_pss[img * STRIPS + threadIdx.x];
    }
    __syncthreads();
    #pragma unroll
    for (int o = STRIPS / 2; o > 0; o >>= 1) {
        if (threadIdx.x < o) {
            rs[threadIdx.x]  += rs[threadIdx.x + o];
            rss[threadIdx.x] += rss[threadIdx.x + o];
        }
        __syncthreads();
    }
    if (threadIdx.x == 0) {
        const double N = (double)HDIM * WDIM;
        double mm  = rs[0] / N;
        double var = rss[0] / N - mm * mm;
        s_mean = (float)mm;
        // o = 0.5*z + 0.5 with IN eps=1e-5  =>  normalize z with eps' = 4e-5
        s_inv = (float)rsqrt(var + 4e-5);
    }
    __syncthreads();
    const float m = s_mean, inv = s_inv;

    #pragma unroll
    for (int i = 0; i < RSTRIP; i++) {
        if (i < RSTRIP - 2) {
            const int rel = (i + 4) % 5;
            load_row_t<INTERIOR>(base, r0 + i + 3, col, v[rel], l[rel], r[rel]);
        }
        const int a = i % 5, b = (i + 1) % 5, c = (i + 2) % 5;
        float z[4];
        stencil4(v[a], l[a], r[a], v[b], l[b], r[b], v[c], l[c], r[c], z);
        float4 o;
        o.x = (z[0] - m) * inv;
        o.y = (z[1] - m) * inv;
        o.z = (z[2] - m) * inv;
        o.w = (z[3] - m) * inv;
        // Evict-first store: output is never re-read; don't pollute L2.
        __stcs((float4*)(obase + (size_t)(r0 + i) * WDIM + col), o);
    }
}

__global__ void __launch_bounds__(256) ltpe_pass2(const float* __restrict__ x,
                                                  float* __restrict__ out) {
    int strip = blockIdx.x % STRIPS;
    int img   = blockIdx.x / STRIPS;
    int r0    = strip * RSTRIP;
    const float* base  = x   + (size_t)img * HDIM * WDIM;
    float*       obase = out + (size_t)img * HDIM * WDIM;
    int col = threadIdx.x * 4;

    if (strip != 0 && strip != STRIPS - 1) pass2_strip<true >(base, obase, r0, col, img);
    else                                   pass2_strip<false>(base, obase, r0, col, img);
}

extern "C" void kernel_launch(void* const* d_in, const int* in_sizes, int n_in,
                              void* d_out, int out_size) {
    const float* x   = (const float*)d_in[0];
    float*       out = (float*)d_out;

    ltpe_pass1<<<NBLOCKS, 256>>>(x);
    ltpe_pass2<<<NBLOCKS, 256>>>(x, out);
}

// round 6
// speedup vs baseline: 1.6475x; 1.0266x over previous
#include <cuda_runtime.h>

// x: (32, 1, 1024, 1024) fp32. out same shape.
#define IMG_N 32
#define HDIM  1024
#define WDIM  1024
#define RSTRIP 16                      // rows per block strip
#define STRIPS (HDIM / RSTRIP)         // 64 strips per image
#define NBLOCKS (IMG_N * STRIPS)       // 2048 blocks per pass

// Per-block partial sums (written unconditionally by pass1 -> no zeroing needed).
__device__ double g_psum[NBLOCKS];
__device__ double g_pss[NBLOCKS];

// Load one row's 4-wide vector; edge lanes additionally load the cross-warp
// halo scalar (predicated off for the 30 interior lanes).
template<bool INTERIOR>
__device__ __forceinline__ void load_row_t(const float* __restrict__ base, int row,
                                           int col, int lane,
                                           float4& v, float& el, float& er) {
    if (!INTERIOR) {
        if (row < 0 || row >= HDIM) {
            v = make_float4(0.f, 0.f, 0.f, 0.f); el = 0.f; er = 0.f; return;
        }
    }
    const float* p = base + (size_t)row * WDIM;
    v = *(const float4*)(p + col);
    el = 0.f; er = 0.f;
    if (lane == 0  && col > 0)        el = __ldg(p + col - 1);
    if (lane == 31 && col + 4 < WDIM) er = __ldg(p + col + 4);
}

// Derive this lane's left/right halo from neighbor lanes (edge lanes use the
// scalar they loaded). Issued lazily at first consume to keep the pipeline.
__device__ __forceinline__ void make_halo(const float4& v, float el, float er,
                                          int lane, float& l, float& r) {
    float lu = __shfl_up_sync(0xffffffffu,  v.w, 1);
    float rd = __shfl_down_sync(0xffffffffu, v.x, 1);
    l = (lane == 0)  ? el : lu;
    r = (lane == 31) ? er : rd;
}

// z = center - (L + 2*DL + 4*D + 8*DR + 16*R + 32*UR + 64*U + 128*UL)/255
// u = row-1, d = row+1 (matches reference offsets; zero padding outside).
__device__ __forceinline__ void stencil4(const float4& u, float ul, float ur,
                                         const float4& c, float cl, float cr,
                                         const float4& d, float dl, float dr,
                                         float z[4]) {
    const float INV255 = 1.0f / 255.0f;
    z[0] = c.x - (cl  + 2.f*dl  + 4.f*d.x + 8.f*d.y + 16.f*c.y + 32.f*u.y + 64.f*u.x + 128.f*ul ) * INV255;
    z[1] = c.y - (c.x + 2.f*d.x + 4.f*d.y + 8.f*d.z + 16.f*c.z + 32.f*u.z + 64.f*u.y + 128.f*u.x) * INV255;
    z[2] = c.z - (c.y + 2.f*d.y + 4.f*d.z + 8.f*d.w + 16.f*c.w + 32.f*u.w + 64.f*u.z + 128.f*u.y) * INV255;
    z[3] = c.w - (c.z + 2.f*d.z + 4.f*d.w + 8.f*dr  + 16.f*cr  + 32.f*ur  + 64.f*u.w + 128.f*u.z) * INV255;
}

// ============ Pass 1: stats (sum z, sum z^2) over each 16-row strip ==========
// Ring of 5 rows: at iter i, issue load of abs row r0+i+3; compute halo for the
// newly-consumed "down" row (r0+i+1); stencil rows (i-1, i, i+1).
template<bool INTERIOR>
__device__ __forceinline__ void pass1_strip(const float* __restrict__ base,
                                            int r0, int col, int lane,
                                            float& s, float& ss) {
    float4 v[5]; float el[5], er[5], l[5], r[5];
    #pragma unroll
    for (int k = 0; k < 4; k++)
        load_row_t<INTERIOR>(base, r0 - 1 + k, col, lane, v[k], el[k], er[k]);
    make_halo(v[0], el[0], er[0], lane, l[0], r[0]);   // row r0-1 (u at iter 0)
    make_halo(v[1], el[1], er[1], lane, l[1], r[1]);   // row r0   (c at iter 0)

    s = 0.f; ss = 0.f;
    #pragma unroll
    for (int i = 0; i < RSTRIP; i++) {
        if (i < RSTRIP - 2) {                    // load abs row r0+i+3
            const int rel = (i + 4) % 5;
            load_row_t<INTERIOR>(base, r0 + i + 3, col, lane, v[rel], el[rel], er[rel]);
        }
        const int a = i % 5, b = (i + 1) % 5, c = (i + 2) % 5;
        make_halo(v[c], el[c], er[c], lane, l[c], r[c]);   // row r0+i+1 debuts as 'd'
        float z[4];
        stencil4(v[a], l[a], r[a], v[b], l[b], r[b], v[c], l[c], r[c], z);
        s  += (z[0] + z[1]) + (z[2] + z[3]);
        ss += (z[0]*z[0] + z[1]*z[1]) + (z[2]*z[2] + z[3]*z[3]);
    }
}

__global__ void __launch_bounds__(256) ltpe_pass1(const float* __restrict__ x) {
    int strip = blockIdx.x % STRIPS;
    int img   = blockIdx.x / STRIPS;
    int r0    = strip * RSTRIP;
    const float* base = x + (size_t)img * HDIM * WDIM;
    int col  = threadIdx.x * 4;
    int lane = threadIdx.x & 31;

    float s, ss;
    if (strip != 0 && strip != STRIPS - 1) pass1_strip<true >(base, r0, col, lane, s, ss);
    else                                   pass1_strip<false>(base, r0, col, lane, s, ss);

    #pragma unroll
    for (int o = 16; o > 0; o >>= 1) {
        s  += __shfl_xor_sync(0xffffffffu, s,  o);
        ss += __shfl_xor_sync(0xffffffffu, ss, o);
    }
    __shared__ float ws[8], wss[8];
    int wid = threadIdx.x >> 5;
    if (lane == 0) { ws[wid] = s; wss[wid] = ss; }
    __syncthreads();
    if (threadIdx.x == 0) {
        float S = 0.f, SS = 0.f;
        #pragma unroll
        for (int i = 0; i < 8; i++) { S += ws[i]; SS += wss[i]; }
        g_psum[blockIdx.x] = (double)S;
        g_pss[blockIdx.x]  = (double)SS;
    }
}

// ============ Pass 2: recompute stencil, normalize, stream out ===============
template<bool INTERIOR>
__device__ __forceinline__ void pass2_strip(const float* __restrict__ base,
                                            float* __restrict__ obase,
                                            int r0, int col, int lane, int img) {
    float4 v[5]; float el[5], er[5], l[5], r[5];
    // Pixel preloads FIRST so the DRAM round-trip overlaps the stats reduce.
    #pragma unroll
    for (int k = 0; k < 4; k++)
        load_row_t<INTERIOR>(base, r0 - 1 + k, col, lane, v[k], el[k], er[k]);

    // Fixed-order stats reduction (deterministic).
    __shared__ double rs[STRIPS], rss[STRIPS];
    __shared__ float s_mean, s_inv;
    if (threadIdx.x < STRIPS) {
        rs[threadIdx.x]  = g_psum[img * STRIPS + threadIdx.x];
        rss[threadIdx.x] = g_pss[img * STRIPS + threadIdx.x];
    }
    __syncthreads();
    #pragma unroll
    for (int o = STRIPS / 2; o > 0; o >>= 1) {
        if (threadIdx.x < o) {
            rs[threadIdx.x]  += rs[threadIdx.x + o];
            rss[threadIdx.x] += rss[threadIdx.x + o];
        }
        __syncthreads();
    }
    if (threadIdx.x == 0) {
        const double N = (double)HDIM * WDIM;
        double mm  = rs[0] / N;
        double var = rss[0] / N - mm * mm;
        s_mean = (float)mm;
        // o = 0.5*z + 0.5 with IN eps=1e-5  =>  normalize z with eps' = 4e-5
        s_inv = (float)rsqrt(var + 4e-5);
    }
    __syncthreads();
    const float m = s_mean, inv = s_inv;

    make_halo(v[0], el[0], er[0], lane, l[0], r[0]);
    make_halo(v[1], el[1], er[1], lane, l[1], r[1]);

    #pragma unroll
    for (int i = 0; i < RSTRIP; i++) {
        if (i < RSTRIP - 2) {
            const int rel = (i + 4) % 5;
            load_row_t<INTERIOR>(base, r0 + i + 3, col, lane, v[rel], el[rel], er[rel]);
        }
        const int a = i % 5, b = (i + 1) % 5, c = (i + 2) % 5;
        make_halo(v[c], el[c], er[c], lane, l[c], r[c]);
        float z[4];
        stencil4(v[a], l[a], r[a], v[b], l[b], r[b], v[c], l[c], r[c], z);
        float4 o;
        o.x = (z[0] - m) * inv;
        o.y = (z[1] - m) * inv;
        o.z = (z[2] - m) * inv;
        o.w = (z[3] - m) * inv;
        // Evict-first store: output is never re-read; don't pollute L2.
        __stcs((float4*)(obase + (size_t)(r0 + i) * WDIM + col), o);
    }
}

__global__ void __launch_bounds__(256) ltpe_pass2(const float* __restrict__ x,
                                                  float* __restrict__ out) {
    int strip = blockIdx.x % STRIPS;
    int img   = blockIdx.x / STRIPS;
    int r0    = strip * RSTRIP;
    const float* base  = x   + (size_t)img * HDIM * WDIM;
    float*       obase = out + (size_t)img * HDIM * WDIM;
    int col  = threadIdx.x * 4;
    int lane = threadIdx.x & 31;

    if (strip != 0 && strip != STRIPS - 1) pass2_strip<true >(base, obase, r0, col, lane, img);
    else                                   pass2_strip<false>(base, obase, r0, col, lane, img);
}

extern "C" void kernel_launch(void* const* d_in, const int* in_sizes, int n_in,
                              void* d_out, int out_size) {
    const float* x   = (const float*)d_in[0];
    float*       out = (float*)d_out;

    ltpe_pass1<<<NBLOCKS, 256>>>(x);
    ltpe_pass2<<<NBLOCKS, 256>>>(x, out);
}

// round 7
// speedup vs baseline: 1.8480x; 1.1217x over previous
#include <cuda_runtime.h>

// x: (32, 1, 1024, 1024) fp32. out same shape.
#define IMG_N 32
#define HDIM  1024
#define WDIM  1024
#define RSTRIP 16                      // rows per block strip
#define STRIPS (HDIM / RSTRIP)         // 64 strips per image
#define NBLOCKS (IMG_N * STRIPS)       // 2048 blocks per pass
#define RING 6                         // rows in flight (distance-3 pipeline)

// Per-block partial sums (written unconditionally by pass1 -> no zeroing needed).
__device__ double g_psum[NBLOCKS];
__device__ double g_pss[NBLOCKS];

// Load one row's 4-wide vector; edge lanes additionally load the cross-warp
// halo scalar (predicated off for the 30 interior lanes).
template<bool INTERIOR>
__device__ __forceinline__ void load_row_t(const float* __restrict__ base, int row,
                                           int col, int lane,
                                           float4& v, float& el, float& er) {
    if (!INTERIOR) {
        if (row < 0 || row >= HDIM) {
            v = make_float4(0.f, 0.f, 0.f, 0.f); el = 0.f; er = 0.f; return;
        }
    }
    const float* p = base + (size_t)row * WDIM;
    v = *(const float4*)(p + col);
    el = 0.f; er = 0.f;
    if (lane == 0  && col > 0)        el = __ldg(p + col - 1);
    if (lane == 31 && col + 4 < WDIM) er = __ldg(p + col + 4);
}

// Derive this lane's left/right halo from neighbor lanes (edge lanes use the
// scalar they loaded). Issued lazily at first consume to keep the pipeline.
__device__ __forceinline__ void make_halo(const float4& v, float el, float er,
                                          int lane, float& l, float& r) {
    float lu = __shfl_up_sync(0xffffffffu,  v.w, 1);
    float rd = __shfl_down_sync(0xffffffffu, v.x, 1);
    l = (lane == 0)  ? el : lu;
    r = (lane == 31) ? er : rd;
}

// z = center - (L + 2*DL + 4*D + 8*DR + 16*R + 32*UR + 64*U + 128*UL)/255
// u = row-1, d = row+1 (matches reference offsets; zero padding outside).
__device__ __forceinline__ void stencil4(const float4& u, float ul, float ur,
                                         const float4& c, float cl, float cr,
                                         const float4& d, float dl, float dr,
                                         float z[4]) {
    const float INV255 = 1.0f / 255.0f;
    z[0] = c.x - (cl  + 2.f*dl  + 4.f*d.x + 8.f*d.y + 16.f*c.y + 32.f*u.y + 64.f*u.x + 128.f*ul ) * INV255;
    z[1] = c.y - (c.x + 2.f*d.x + 4.f*d.y + 8.f*d.z + 16.f*c.z + 32.f*u.z + 64.f*u.y + 128.f*u.x) * INV255;
    z[2] = c.z - (c.y + 2.f*d.y + 4.f*d.z + 8.f*d.w + 16.f*c.w + 32.f*u.w + 64.f*u.z + 128.f*u.y) * INV255;
    z[3] = c.w - (c.z + 2.f*d.z + 4.f*d.w + 8.f*dr  + 16.f*cr  + 32.f*ur  + 64.f*u.w + 128.f*u.z) * INV255;
}

// ============ Pass 1: stats (sum z, sum z^2) over each 16-row strip ==========
// Ring of RING=6 rows, distance-3 pipeline: at iter i, issue load of abs row
// r0+i+4; halo for the newly-consumed 'down' row; stencil rows (i-1, i, i+1).
template<bool INTERIOR>
__device__ __forceinline__ void pass1_strip(const float* __restrict__ base,
                                            int r0, int col, int lane,
                                            float& s, float& ss) {
    float4 v[RING]; float el[RING], er[RING], l[RING], r[RING];
    #pragma unroll
    for (int k = 0; k < RING - 1; k++)            // abs rows r0-1 .. r0+3
        load_row_t<INTERIOR>(base, r0 - 1 + k, col, lane, v[k], el[k], er[k]);
    make_halo(v[0], el[0], er[0], lane, l[0], r[0]);   // row r0-1 (u at iter 0)
    make_halo(v[1], el[1], er[1], lane, l[1], r[1]);   // row r0   (c at iter 0)

    s = 0.f; ss = 0.f;
    #pragma unroll
    for (int i = 0; i < RSTRIP; i++) {
        if (i < RSTRIP - 3) {                    // load abs row r0+i+4
            const int rel = (i + RING - 1) % RING;
            load_row_t<INTERIOR>(base, r0 + i + 4, col, lane, v[rel], el[rel], er[rel]);
        }
        const int a = i % RING, b = (i + 1) % RING, c = (i + 2) % RING;
        make_halo(v[c], el[c], er[c], lane, l[c], r[c]);   // row r0+i+1 debuts as 'd'
        float z[4];
        stencil4(v[a], l[a], r[a], v[b], l[b], r[b], v[c], l[c], r[c], z);
        s  += (z[0] + z[1]) + (z[2] + z[3]);
        ss += (z[0]*z[0] + z[1]*z[1]) + (z[2]*z[2] + z[3]*z[3]);
    }
}

__global__ void __launch_bounds__(256) ltpe_pass1(const float* __restrict__ x) {
    int strip = blockIdx.x % STRIPS;
    int img   = blockIdx.x / STRIPS;
    int r0    = strip * RSTRIP;
    const float* base = x + (size_t)img * HDIM * WDIM;
    int col  = threadIdx.x * 4;
    int lane = threadIdx.x & 31;

    float s, ss;
    if (strip != 0 && strip != STRIPS - 1) pass1_strip<true >(base, r0, col, lane, s, ss);
    else                                   pass1_strip<false>(base, r0, col, lane, s, ss);

    #pragma unroll
    for (int o = 16; o > 0; o >>= 1) {
        s  += __shfl_xor_sync(0xffffffffu, s,  o);
        ss += __shfl_xor_sync(0xffffffffu, ss, o);
    }
    __shared__ float ws[8], wss[8];
    int wid = threadIdx.x >> 5;
    if (lane == 0) { ws[wid] = s; wss[wid] = ss; }
    __syncthreads();
    if (threadIdx.x == 0) {
        float S = 0.f, SS = 0.f;
        #pragma unroll
        for (int i = 0; i < 8; i++) { S += ws[i]; SS += wss[i]; }
        g_psum[blockIdx.x] = (double)S;
        g_pss[blockIdx.x]  = (double)SS;
    }
}

// ============ Pass 2: recompute stencil, normalize, stream out ===============
template<bool INTERIOR>
__device__ __forceinline__ void pass2_strip(const float* __restrict__ base,
                                            float* __restrict__ obase,
                                            int r0, int col, int lane, int img) {
    float4 v[RING]; float el[RING], er[RING], l[RING], r[RING];
    // Pixel preloads FIRST so the DRAM round-trip overlaps the stats reduce.
    #pragma unroll
    for (int k = 0; k < RING - 1; k++)
        load_row_t<INTERIOR>(base, r0 - 1 + k, col, lane, v[k], el[k], er[k]);

    // Fixed-order stats reduction (deterministic).
    __shared__ double rs[STRIPS], rss[STRIPS];
    __shared__ float s_mean, s_inv;
    if (threadIdx.x < STRIPS) {
        rs[threadIdx.x]  = g_psum[img * STRIPS + threadIdx.x];
        rss[threadIdx.x] = g_pss[img * STRIPS + threadIdx.x];
    }
    __syncthreads();
    #pragma unroll
    for (int o = STRIPS / 2; o > 0; o >>= 1) {
        if (threadIdx.x < o) {
            rs[threadIdx.x]  += rs[threadIdx.x + o];
            rss[threadIdx.x] += rss[threadIdx.x + o];
        }
        __syncthreads();
    }
    if (threadIdx.x == 0) {
        const double N = (double)HDIM * WDIM;
        double mm  = rs[0] / N;
        double var = rss[0] / N - mm * mm;
        s_mean = (float)mm;
        // o = 0.5*z + 0.5 with IN eps=1e-5  =>  normalize z with eps' = 4e-5
        s_inv = (float)rsqrt(var + 4e-5);
    }
    __syncthreads();
    const float m = s_mean, inv = s_inv;

    make_halo(v[0], el[0], er[0], lane, l[0], r[0]);
    make_halo(v[1], el[1], er[1], lane, l[1], r[1]);

    #pragma unroll
    for (int i = 0; i < RSTRIP; i++) {
        if (i < RSTRIP - 3) {
            const int rel = (i + RING - 1) % RING;
            load_row_t<INTERIOR>(base, r0 + i + 4, col, lane, v[rel], el[rel], er[rel]);
        }
        const int a = i % RING, b = (i + 1) % RING, c = (i + 2) % RING;
        make_halo(v[c], el[c], er[c], lane, l[c], r[c]);
        float z[4];
        stencil4(v[a], l[a], r[a], v[b], l[b], r[b], v[c], l[c], r[c], z);
        float4 o;
        o.x = (z[0] - m) * inv;
        o.y = (z[1] - m) * inv;
        o.z = (z[2] - m) * inv;
        o.w = (z[3] - m) * inv;
        // Evict-first store: output is never re-read; don't displace x in L2.
        __stcs((float4*)(obase + (size_t)(r0 + i) * WDIM + col), o);
    }
}

__global__ void __launch_bounds__(256) ltpe_pass2(const float* __restrict__ x,
                                                  float* __restrict__ out) {
    // REVERSE block order: pass1 streamed x forward, so L2 (~126MB) holds the
    // tail of x (~all but the first few MB). Walking backward, pass2 reads the
    // hottest lines first and stays inside the resident window; its own stores
    // are evict-first. Under graph replay this also leaves the head of x warm
    // for the next iteration's forward pass1.
    int bid   = (NBLOCKS - 1) - blockIdx.x;
    int strip = bid % STRIPS;
    int img   = bid / STRIPS;
    int r0    = strip * RSTRIP;
    const float* base  = x   + (size_t)img * HDIM * WDIM;
    float*       obase = out + (size_t)img * HDIM * WDIM;
    int col  = threadIdx.x * 4;
    int lane = threadIdx.x & 31;

    if (strip != 0 && strip != STRIPS - 1) pass2_strip<true >(base, obase, r0, col, lane, img);
    else                                   pass2_strip<false>(base, obase, r0, col, lane, img);
}

extern "C" void kernel_launch(void* const* d_in, const int* in_sizes, int n_in,
                              void* d_out, int out_size) {
    const float* x   = (const float*)d_in[0];
    float*       out = (float*)d_out;

    ltpe_pass1<<<NBLOCKS, 256>>>(x);
    ltpe_pass2<<<NBLOCKS, 256>>>(x, out);
}